// round 5
// baseline (speedup 1.0000x reference)
#include <cuda_runtime.h>

#define N_NODES 40000
#define N_EDGES 640000
#define NFEAT   256
#define NHID    128

// Scratch for support = x @ W  (20.5 MB, device global: no allocations allowed)
__device__ float g_support[N_NODES * NHID];

// ---------------------------------------------------------------------------
// GEMM: support[N_NODES, NHID] = x[N_NODES, NFEAT] @ W[NFEAT, NHID]
// BM=64, BN=128 (full width), BK=32. 256 threads, each computes 8x4 outputs.
// ---------------------------------------------------------------------------
#define BM 64
#define BK 32

__global__ __launch_bounds__(256) void gemm_kernel(const float* __restrict__ x,
                                                   const float* __restrict__ W) {
    __shared__ float xs[BK][BM];        // transposed x tile: xs[k][row]
    __shared__ float ws[BK][NHID];      // W tile: ws[k][col]

    const int tid = threadIdx.x;
    const int block_row = blockIdx.x * BM;

    // thread -> 8x4 microtile
    const int rowg = tid >> 5;          // 0..7   (group of 8 rows)
    const int colg = tid & 31;          // 0..31  (group of 4 cols)
    const int r0 = rowg * 8;
    const int c0 = colg * 4;

    float acc[8][4];
#pragma unroll
    for (int i = 0; i < 8; i++)
#pragma unroll
        for (int j = 0; j < 4; j++) acc[i][j] = 0.f;

    // x-tile load mapping: 64 rows x 32 cols = 512 float4, 256 thr -> 2 each
    const int lx_r = tid >> 3;              // 0..31  (two rows per thread: lx_r, lx_r+32)
    const int lx_c = (tid & 7) * 4;         // 0..28

    for (int k0 = 0; k0 < NFEAT; k0 += BK) {
        // load x tile (transposed store)
#pragma unroll
        for (int rr = 0; rr < 2; rr++) {
            int row = lx_r + rr * 32;
            float4 v = *(const float4*)(x + (size_t)(block_row + row) * NFEAT + k0 + lx_c);
            xs[lx_c + 0][row] = v.x;
            xs[lx_c + 1][row] = v.y;
            xs[lx_c + 2][row] = v.z;
            xs[lx_c + 3][row] = v.w;
        }
        // load W tile: 32 rows x 128 cols = 1024 float4, 4 per thread
#pragma unroll
        for (int t = 0; t < 4; t++) {
            int idx = tid + t * 256;        // float4 index in [0,1024)
            int wr = idx >> 5;              // 0..31
            int wc = (idx & 31) * 4;        // 0..124
            float4 v = *(const float4*)(W + (size_t)(k0 + wr) * NHID + wc);
            *(float4*)&ws[wr][wc] = v;
        }
        __syncthreads();

#pragma unroll
        for (int kk = 0; kk < BK; kk++) {
            float a[8];
#pragma unroll
            for (int i = 0; i < 8; i++) a[i] = xs[kk][r0 + i];   // broadcast within warp
            float4 b4 = *(const float4*)&ws[kk][c0];             // LDS.128, conflict-free
            float b[4] = {b4.x, b4.y, b4.z, b4.w};
#pragma unroll
            for (int i = 0; i < 8; i++)
#pragma unroll
                for (int j = 0; j < 4; j++) acc[i][j] = fmaf(a[i], b[j], acc[i][j]);
        }
        __syncthreads();
    }

#pragma unroll
    for (int i = 0; i < 8; i++) {
        float4 v = make_float4(acc[i][0], acc[i][1], acc[i][2], acc[i][3]);
        *(float4*)(g_support + (size_t)(block_row + r0 + i) * NHID + c0) = v;
    }
}

// ---------------------------------------------------------------------------
// Scatter: one warp per edge. lane handles 4 columns via float4 + red.v4.f32.
// edge_index arrives as int32 (harness converts int64 -> int32).
// ---------------------------------------------------------------------------
__global__ __launch_bounds__(256) void scatter_kernel(const int* __restrict__ ei,
                                                      const float* __restrict__ ew,
                                                      float* __restrict__ out) {
    const int warp = (blockIdx.x * blockDim.x + threadIdx.x) >> 5;
    const int lane = threadIdx.x & 31;
    if (warp >= N_EDGES) return;

    const int   src = __ldg(ei + warp);
    const int   dst = __ldg(ei + N_EDGES + warp);
    const float w   = __ldg(ew + warp);

    float4 v = *(const float4*)(g_support + (size_t)src * NHID + lane * 4);
    v.x *= w; v.y *= w; v.z *= w; v.w *= w;

    float* addr = out + (size_t)dst * NHID + lane * 4;
    asm volatile("red.global.add.v4.f32 [%0], {%1, %2, %3, %4};"
                 :: "l"(addr), "f"(v.x), "f"(v.y), "f"(v.z), "f"(v.w)
                 : "memory");
}

// ---------------------------------------------------------------------------
// Epilogue: out = relu(out + b), vectorized float4.
// ---------------------------------------------------------------------------
__global__ __launch_bounds__(256) void bias_relu_kernel(float* __restrict__ out,
                                                        const float* __restrict__ b) {
    const int idx = blockIdx.x * blockDim.x + threadIdx.x;   // float4 index
    const int total = N_NODES * NHID / 4;
    if (idx >= total) return;
    const int c4 = (idx & 31) * 4;   // column within 128, in float4 units
    float4 v = ((float4*)out)[idx];
    float4 bb = *(const float4*)(b + c4);
    v.x += bb.x; v.y += bb.y; v.z += bb.z; v.w += bb.w;
    v.x = fmaxf(v.x, 0.f);
    v.y = fmaxf(v.y, 0.f);
    v.z = fmaxf(v.z, 0.f);
    v.w = fmaxf(v.w, 0.f);
    ((float4*)out)[idx] = v;
}

// ---------------------------------------------------------------------------
extern "C" void kernel_launch(void* const* d_in, const int* in_sizes, int n_in,
                              void* d_out, int out_size) {
    const float* x  = (const float*)d_in[0];
    const int*   ei = (const int*)d_in[1];     // int32 on device
    const float* ew = (const float*)d_in[2];
    const float* W  = (const float*)d_in[3];
    const float* b  = (const float*)d_in[4];
    float*       out = (float*)d_out;

    // 1) support = x @ W
    gemm_kernel<<<N_NODES / BM, 256>>>(x, W);

    // 2) zero output (d_out is poisoned), then scatter-add messages
    cudaMemsetAsync(out, 0, (size_t)N_NODES * NHID * sizeof(float));
    scatter_kernel<<<(N_EDGES * 32) / 256, 256>>>(ei, ew, out);

    // 3) out = relu(out + b)
    bias_relu_kernel<<<(N_NODES * NHID / 4 + 255) / 256, 256>>>(out, b);
}

// round 6
// speedup vs baseline: 1.2512x; 1.2512x over previous
#include <cuda_runtime.h>

#define N_NODES 40000
#define N_EDGES 640000
#define NFEAT   256
#define NHID    128

// ---- device-global scratch (no allocations allowed) ----
__device__ float g_support[N_NODES * NHID];   // x @ W
__device__ int   g_cnt [N_NODES];             // in-degree per dst
__device__ int   g_fill[N_NODES];             // fill cursors
__device__ int   g_off [N_NODES];             // exclusive prefix of cnt
__device__ int   g_bsum[160];                 // per-block scan sums
__device__ int2  g_edge[N_EDGES];             // CSR payload: {src, bits(w)}

// ---------------------------------------------------------------------------
// helpers: packed f32x2 FMA (Blackwell FFMA2 — only reachable via PTX)
// ---------------------------------------------------------------------------
__device__ __forceinline__ void fma2(unsigned long long& d,
                                     unsigned long long a,
                                     unsigned long long b) {
    asm("fma.rn.f32x2 %0, %1, %2, %0;" : "+l"(d) : "l"(a), "l"(b));
}
__device__ __forceinline__ unsigned long long dup2(float s) {
    unsigned long long d;
    asm("mov.b64 %0, {%1, %1};" : "=l"(d) : "f"(s));
    return d;
}
__device__ __forceinline__ float f2lo(unsigned long long v) {
    return __uint_as_float((unsigned)v);
}
__device__ __forceinline__ float f2hi(unsigned long long v) {
    return __uint_as_float((unsigned)(v >> 32));
}

// ---------------------------------------------------------------------------
// GEMM: support = x @ W.  BM=64, BN=128, BK=32, 256 thr, 8x4 microtile,
// accumulated as 4 row-pairs x 4 cols of f32x2.
// ---------------------------------------------------------------------------
#define BM 64
#define BK 32

__global__ __launch_bounds__(256) void gemm_kernel(const float* __restrict__ x,
                                                   const float* __restrict__ W) {
    __shared__ float xs[BK][BM];        // transposed x tile: xs[k][row]
    __shared__ float ws[BK][NHID];      // W tile: ws[k][col]

    const int tid = threadIdx.x;
    const int block_row = blockIdx.x * BM;
    const int rowg = tid >> 5;          // 0..7
    const int colg = tid & 31;          // 0..31
    const int r0 = rowg * 8;
    const int c0 = colg * 4;

    unsigned long long acc[4][4];       // [row-pair][col], f32x2 packed
#pragma unroll
    for (int p = 0; p < 4; p++)
#pragma unroll
        for (int j = 0; j < 4; j++) acc[p][j] = 0ULL;

    const int lx_r = tid >> 3;          // 0..31
    const int lx_c = (tid & 7) * 4;     // 0..28

    for (int k0 = 0; k0 < NFEAT; k0 += BK) {
        // x tile (transposed store)
#pragma unroll
        for (int rr = 0; rr < 2; rr++) {
            int row = lx_r + rr * 32;
            float4 v = *(const float4*)(x + (size_t)(block_row + row) * NFEAT + k0 + lx_c);
            xs[lx_c + 0][row] = v.x;
            xs[lx_c + 1][row] = v.y;
            xs[lx_c + 2][row] = v.z;
            xs[lx_c + 3][row] = v.w;
        }
        // W tile: 32 rows x 128 cols = 1024 float4, 4 per thread
#pragma unroll
        for (int t = 0; t < 4; t++) {
            int idx = tid + t * 256;
            int wr = idx >> 5;
            int wc = (idx & 31) * 4;
            *(float4*)&ws[wr][wc] = *(const float4*)(W + (size_t)(k0 + wr) * NHID + wc);
        }
        __syncthreads();

#pragma unroll
        for (int kk = 0; kk < BK; kk++) {
            // 4 row-pairs, loaded directly as packed 64-bit lanes (broadcast)
            ulonglong2 a01 = *(const ulonglong2*)&xs[kk][r0];
            ulonglong2 a23 = *(const ulonglong2*)&xs[kk][r0 + 4];
            float4 b4 = *(const float4*)&ws[kk][c0];      // dense LDS.128
            unsigned long long bd[4] = {dup2(b4.x), dup2(b4.y), dup2(b4.z), dup2(b4.w)};
#pragma unroll
            for (int j = 0; j < 4; j++) {
                fma2(acc[0][j], a01.x, bd[j]);
                fma2(acc[1][j], a01.y, bd[j]);
                fma2(acc[2][j], a23.x, bd[j]);
                fma2(acc[3][j], a23.y, bd[j]);
            }
        }
        __syncthreads();
    }

#pragma unroll
    for (int p = 0; p < 4; p++) {
        float4 vlo = make_float4(f2lo(acc[p][0]), f2lo(acc[p][1]), f2lo(acc[p][2]), f2lo(acc[p][3]));
        float4 vhi = make_float4(f2hi(acc[p][0]), f2hi(acc[p][1]), f2hi(acc[p][2]), f2hi(acc[p][3]));
        *(float4*)(g_support + (size_t)(block_row + r0 + 2 * p)     * NHID + c0) = vlo;
        *(float4*)(g_support + (size_t)(block_row + r0 + 2 * p + 1) * NHID + c0) = vhi;
    }
}

// ---------------------------------------------------------------------------
// CSR build: zero counters -> histogram -> 3-kernel scan -> fill
// ---------------------------------------------------------------------------
__global__ __launch_bounds__(256) void zero_counters_kernel() {
    int i = blockIdx.x * 256 + threadIdx.x;
    if (i < N_NODES) { g_cnt[i] = 0; g_fill[i] = 0; }
}

__global__ __launch_bounds__(256) void hist_kernel(const int* __restrict__ ei) {
    int i = blockIdx.x * 256 + threadIdx.x;
    if (i < N_EDGES) atomicAdd(&g_cnt[ei[N_EDGES + i]], 1);
}

// block-local exclusive scan over 256 ints; returns excl prefix, sets *total
__device__ __forceinline__ int block_excl_scan(int v, int tid, int* smem_warp, int* total) {
    int lane = tid & 31, wid = tid >> 5;
    int x = v;
#pragma unroll
    for (int d = 1; d < 32; d <<= 1) {
        int y = __shfl_up_sync(0xffffffffu, x, d);
        if (lane >= d) x += y;
    }                                       // inclusive within warp
    if (lane == 31) smem_warp[wid] = x;
    __syncthreads();
    if (wid == 0) {
        int y = (lane < 8) ? smem_warp[lane] : 0;
#pragma unroll
        for (int d = 1; d < 8; d <<= 1) {
            int z = __shfl_up_sync(0xffffffffu, y, d);
            if (lane >= d) y += z;
        }
        if (lane < 8) smem_warp[lane] = y;  // inclusive warp totals
    }
    __syncthreads();
    int base = (wid > 0) ? smem_warp[wid - 1] : 0;
    *total = smem_warp[7];
    return base + x - v;                    // exclusive prefix
}

__global__ __launch_bounds__(256) void scan1_kernel() {   // per-block scan
    __shared__ int sw[8];
    int tid = threadIdx.x;
    int i = blockIdx.x * 256 + tid;
    int v = (i < N_NODES) ? g_cnt[i] : 0;
    int total;
    int e = block_excl_scan(v, tid, sw, &total);
    if (i < N_NODES) g_off[i] = e;
    if (tid == 0) g_bsum[blockIdx.x] = total;
}

__global__ __launch_bounds__(256) void scan2_kernel(int nblocks) {  // scan block sums
    __shared__ int sw[8];
    int tid = threadIdx.x;
    int v = (tid < nblocks) ? g_bsum[tid] : 0;
    int total;
    int e = block_excl_scan(v, tid, sw, &total);
    if (tid < nblocks) g_bsum[tid] = e;
}

__global__ __launch_bounds__(256) void scan3_kernel() {   // propagate block bases
    int i = blockIdx.x * 256 + threadIdx.x;
    if (i < N_NODES) g_off[i] += g_bsum[blockIdx.x];
}

__global__ __launch_bounds__(256) void fill_kernel(const int* __restrict__ ei,
                                                   const float* __restrict__ ew) {
    int i = blockIdx.x * 256 + threadIdx.x;
    if (i >= N_EDGES) return;
    int src = ei[i];
    int dst = ei[N_EDGES + i];
    int pos = g_off[dst] + atomicAdd(&g_fill[dst], 1);
    g_edge[pos] = make_int2(src, __float_as_int(ew[i]));
}

// ---------------------------------------------------------------------------
// Aggregate: one warp per dst node; register accumulation; fused bias+relu.
// Writes each output row exactly once (no memset, no RMW, no epilogue).
// ---------------------------------------------------------------------------
__global__ __launch_bounds__(256) void aggregate_kernel(const float* __restrict__ b,
                                                        float* __restrict__ out) {
    const int warp = (blockIdx.x * 256 + threadIdx.x) >> 5;
    const int lane = threadIdx.x & 31;
    if (warp >= N_NODES) return;

    const int off = g_off[warp];
    const int n   = g_cnt[warp];

    float4 acc = make_float4(0.f, 0.f, 0.f, 0.f);
    for (int j = 0; j < n; j++) {
        int2 e = __ldg(&g_edge[off + j]);               // 8B broadcast
        float w = __int_as_float(e.y);
        float4 v = *(const float4*)(g_support + (size_t)e.x * NHID + lane * 4);
        acc.x = fmaf(v.x, w, acc.x);
        acc.y = fmaf(v.y, w, acc.y);
        acc.z = fmaf(v.z, w, acc.z);
        acc.w = fmaf(v.w, w, acc.w);
    }

    float4 bb = *(const float4*)(b + lane * 4);
    float4 r;
    r.x = fmaxf(acc.x + bb.x, 0.f);
    r.y = fmaxf(acc.y + bb.y, 0.f);
    r.z = fmaxf(acc.z + bb.z, 0.f);
    r.w = fmaxf(acc.w + bb.w, 0.f);
    *(float4*)(out + (size_t)warp * NHID + lane * 4) = r;
}

// ---------------------------------------------------------------------------
extern "C" void kernel_launch(void* const* d_in, const int* in_sizes, int n_in,
                              void* d_out, int out_size) {
    const float* x  = (const float*)d_in[0];
    const int*   ei = (const int*)d_in[1];     // int32 on device
    const float* ew = (const float*)d_in[2];
    const float* W  = (const float*)d_in[3];
    const float* b  = (const float*)d_in[4];
    float*       out = (float*)d_out;

    const int NODE_BLKS = (N_NODES + 255) / 256;   // 157
    const int EDGE_BLKS = (N_EDGES + 255) / 256;   // 2500

    gemm_kernel<<<N_NODES / BM, 256>>>(x, W);          // 625 CTAs

    zero_counters_kernel<<<NODE_BLKS, 256>>>();
    hist_kernel<<<EDGE_BLKS, 256>>>(ei);
    scan1_kernel<<<NODE_BLKS, 256>>>();
    scan2_kernel<<<1, 256>>>(NODE_BLKS);
    scan3_kernel<<<NODE_BLKS, 256>>>();
    fill_kernel<<<EDGE_BLKS, 256>>>(ei, ew);

    aggregate_kernel<<<(N_NODES * 32 + 255) / 256, 256>>>(b, out);   // warp/node
}

// round 8
// speedup vs baseline: 1.4009x; 1.1197x over previous
#include <cuda_runtime.h>

#define N_NODES 40000
#define N_EDGES 640000
#define NFEAT   256
#define NHID    128

// ---- device-global scratch (no allocations allowed) ----
__device__ float g_support[N_NODES * NHID];   // x @ W
__device__ int   g_cnt [N_NODES];             // in-degree per dst
__device__ int   g_fill[N_NODES];             // fill cursors
__device__ int   g_off [N_NODES];             // block-local exclusive prefix
__device__ int   g_bsum[160];                 // scanned per-block bases
__device__ int2  g_edge[N_EDGES];             // CSR payload: {src, bits(w)}

// ---------------------------------------------------------------------------
// helpers: packed f32x2 FMA (Blackwell FFMA2 — only reachable via PTX)
// ---------------------------------------------------------------------------
__device__ __forceinline__ void fma2(unsigned long long& d,
                                     unsigned long long a,
                                     unsigned long long b) {
    asm("fma.rn.f32x2 %0, %1, %2, %0;" : "+l"(d) : "l"(a), "l"(b));
}
__device__ __forceinline__ unsigned long long dup2(float s) {
    unsigned long long d;
    asm("mov.b64 %0, {%1, %1};" : "=l"(d) : "f"(s));
    return d;
}
__device__ __forceinline__ float f2lo(unsigned long long v) {
    return __uint_as_float((unsigned)v);
}
__device__ __forceinline__ float f2hi(unsigned long long v) {
    return __uint_as_float((unsigned)(v >> 32));
}

// ---------------------------------------------------------------------------
// GEMM: support = x @ W.  BM=64, BN=128, BK=32, 256 thr, 8x4 microtile,
// accumulated as 4 row-pairs x 4 cols of f32x2.
// ---------------------------------------------------------------------------
#define BM 64
#define BK 32

__global__ __launch_bounds__(256) void gemm_kernel(const float* __restrict__ x,
                                                   const float* __restrict__ W) {
    __shared__ float xs[BK][BM];        // transposed x tile: xs[k][row]
    __shared__ float ws[BK][NHID];      // W tile: ws[k][col]

    const int tid = threadIdx.x;
    const int block_row = blockIdx.x * BM;
    const int rowg = tid >> 5;          // 0..7
    const int colg = tid & 31;          // 0..31
    const int r0 = rowg * 8;
    const int c0 = colg * 4;

    unsigned long long acc[4][4];       // [row-pair][col], f32x2 packed
#pragma unroll
    for (int p = 0; p < 4; p++)
#pragma unroll
        for (int j = 0; j < 4; j++) acc[p][j] = 0ULL;

    const int lx_r = tid >> 3;          // 0..31
    const int lx_c = (tid & 7) * 4;     // 0..28

    for (int k0 = 0; k0 < NFEAT; k0 += BK) {
#pragma unroll
        for (int rr = 0; rr < 2; rr++) {
            int row = lx_r + rr * 32;
            float4 v = *(const float4*)(x + (size_t)(block_row + row) * NFEAT + k0 + lx_c);
            xs[lx_c + 0][row] = v.x;
            xs[lx_c + 1][row] = v.y;
            xs[lx_c + 2][row] = v.z;
            xs[lx_c + 3][row] = v.w;
        }
#pragma unroll
        for (int t = 0; t < 4; t++) {
            int idx = tid + t * 256;
            int wr = idx >> 5;
            int wc = (idx & 31) * 4;
            *(float4*)&ws[wr][wc] = *(const float4*)(W + (size_t)(k0 + wr) * NHID + wc);
        }
        __syncthreads();

#pragma unroll
        for (int kk = 0; kk < BK; kk++) {
            ulonglong2 a01 = *(const ulonglong2*)&xs[kk][r0];
            ulonglong2 a23 = *(const ulonglong2*)&xs[kk][r0 + 4];
            float4 b4 = *(const float4*)&ws[kk][c0];
            unsigned long long bd[4] = {dup2(b4.x), dup2(b4.y), dup2(b4.z), dup2(b4.w)};
#pragma unroll
            for (int j = 0; j < 4; j++) {
                fma2(acc[0][j], a01.x, bd[j]);
                fma2(acc[1][j], a01.y, bd[j]);
                fma2(acc[2][j], a23.x, bd[j]);
                fma2(acc[3][j], a23.y, bd[j]);
            }
        }
        __syncthreads();
    }

#pragma unroll
    for (int p = 0; p < 4; p++) {
        float4 vlo = make_float4(f2lo(acc[p][0]), f2lo(acc[p][1]), f2lo(acc[p][2]), f2lo(acc[p][3]));
        float4 vhi = make_float4(f2hi(acc[p][0]), f2hi(acc[p][1]), f2hi(acc[p][2]), f2hi(acc[p][3]));
        *(float4*)(g_support + (size_t)(block_row + r0 + 2 * p)     * NHID + c0) = vlo;
        *(float4*)(g_support + (size_t)(block_row + r0 + 2 * p + 1) * NHID + c0) = vhi;
    }
}

// ---------------------------------------------------------------------------
// CSR build: memset -> histogram -> 2-level scan (bases folded downstream) -> fill
// ---------------------------------------------------------------------------
__global__ __launch_bounds__(256) void hist_kernel(const int* __restrict__ ei) {
    int i = blockIdx.x * 256 + threadIdx.x;
    if (i < N_EDGES) atomicAdd(&g_cnt[ei[N_EDGES + i]], 1);
}

__device__ __forceinline__ int block_excl_scan(int v, int tid, int* smem_warp, int* total) {
    int lane = tid & 31, wid = tid >> 5;
    int x = v;
#pragma unroll
    for (int d = 1; d < 32; d <<= 1) {
        int y = __shfl_up_sync(0xffffffffu, x, d);
        if (lane >= d) x += y;
    }
    if (lane == 31) smem_warp[wid] = x;
    __syncthreads();
    if (wid == 0) {
        int y = (lane < 8) ? smem_warp[lane] : 0;
#pragma unroll
        for (int d = 1; d < 8; d <<= 1) {
            int z = __shfl_up_sync(0xffffffffu, y, d);
            if (lane >= d) y += z;
        }
        if (lane < 8) smem_warp[lane] = y;
    }
    __syncthreads();
    int base = (wid > 0) ? smem_warp[wid - 1] : 0;
    *total = smem_warp[7];
    return base + x - v;
}

__global__ __launch_bounds__(256) void scan1_kernel() {   // per-block scan
    __shared__ int sw[8];
    int tid = threadIdx.x;
    int i = blockIdx.x * 256 + tid;
    int v = (i < N_NODES) ? g_cnt[i] : 0;
    int total;
    int e = block_excl_scan(v, tid, sw, &total);
    if (i < N_NODES) g_off[i] = e;
    if (tid == 0) g_bsum[blockIdx.x] = total;
}

__global__ __launch_bounds__(256) void scan2_kernel(int nblocks) {  // scan block sums
    __shared__ int sw[8];
    int tid = threadIdx.x;
    int v = (tid < nblocks) ? g_bsum[tid] : 0;
    int total;
    int e = block_excl_scan(v, tid, sw, &total);
    if (tid < nblocks) g_bsum[tid] = e;
}

__global__ __launch_bounds__(256) void fill_kernel(const int* __restrict__ ei,
                                                   const float* __restrict__ ew) {
    int i = blockIdx.x * 256 + threadIdx.x;
    if (i >= N_EDGES) return;
    int src = ei[i];
    int dst = ei[N_EDGES + i];
    int pos = g_off[dst] + g_bsum[dst >> 8] + atomicAdd(&g_fill[dst], 1);
    g_edge[pos] = make_int2(src, __float_as_int(ew[i]));
}

// ---------------------------------------------------------------------------
// Aggregate: one warp per dst node; register accumulation; fused bias+relu.
// 2-edge unroll: two independent gathers in flight per warp.
// ---------------------------------------------------------------------------
__global__ __launch_bounds__(256) void aggregate_kernel(const float* __restrict__ b,
                                                        float* __restrict__ out) {
    const int warp = (blockIdx.x * 256 + threadIdx.x) >> 5;
    const int lane = threadIdx.x & 31;
    if (warp >= N_NODES) return;

    const int off = g_off[warp] + g_bsum[warp >> 8];
    const int n   = g_cnt[warp];

    float4 acc0 = make_float4(0.f, 0.f, 0.f, 0.f);
    float4 acc1 = make_float4(0.f, 0.f, 0.f, 0.f);

    int j = 0;
    for (; j + 2 <= n; j += 2) {
        int2 e0 = __ldg(&g_edge[off + j]);
        int2 e1 = __ldg(&g_edge[off + j + 1]);
        float w0 = __int_as_float(e0.y);
        float w1 = __int_as_float(e1.y);
        float4 v0 = *(const float4*)(g_support + (size_t)e0.x * NHID + lane * 4);
        float4 v1 = *(const float4*)(g_support + (size_t)e1.x * NHID + lane * 4);
        acc0.x = fmaf(v0.x, w0, acc0.x);
        acc0.y = fmaf(v0.y, w0, acc0.y);
        acc0.z = fmaf(v0.z, w0, acc0.z);
        acc0.w = fmaf(v0.w, w0, acc0.w);
        acc1.x = fmaf(v1.x, w1, acc1.x);
        acc1.y = fmaf(v1.y, w1, acc1.y);
        acc1.z = fmaf(v1.z, w1, acc1.z);
        acc1.w = fmaf(v1.w, w1, acc1.w);
    }
    if (j < n) {
        int2 e0 = __ldg(&g_edge[off + j]);
        float w0 = __int_as_float(e0.y);
        float4 v0 = *(const float4*)(g_support + (size_t)e0.x * NHID + lane * 4);
        acc0.x = fmaf(v0.x, w0, acc0.x);
        acc0.y = fmaf(v0.y, w0, acc0.y);
        acc0.z = fmaf(v0.z, w0, acc0.z);
        acc0.w = fmaf(v0.w, w0, acc0.w);
    }

    float4 bb = *(const float4*)(b + lane * 4);
    float4 r;
    r.x = fmaxf(acc0.x + acc1.x + bb.x, 0.f);
    r.y = fmaxf(acc0.y + acc1.y + bb.y, 0.f);
    r.z = fmaxf(acc0.z + acc1.z + bb.z, 0.f);
    r.w = fmaxf(acc0.w + acc1.w + bb.w, 0.f);
    *(float4*)(out + (size_t)warp * NHID + lane * 4) = r;
}

// ---------------------------------------------------------------------------
extern "C" void kernel_launch(void* const* d_in, const int* in_sizes, int n_in,
                              void* d_out, int out_size) {
    const float* x  = (const float*)d_in[0];
    const int*   ei = (const int*)d_in[1];     // int32 on device
    const float* ew = (const float*)d_in[2];
    const float* W  = (const float*)d_in[3];
    const float* b  = (const float*)d_in[4];
    float*       out = (float*)d_out;

    const int NODE_BLKS = (N_NODES + 255) / 256;   // 157
    const int EDGE_BLKS = (N_EDGES + 255) / 256;   // 2500

    // one-time side-stream + event creation (host resources only; per-call
    // device work is identical and fully captured via fork/join events)
    static cudaStream_t s2 = nullptr;
    static cudaEvent_t evFork = nullptr, evJoin = nullptr;
    if (!s2) {
        cudaStreamCreateWithFlags(&s2, cudaStreamNonBlocking);
        cudaEventCreateWithFlags(&evFork, cudaEventDisableTiming);
        cudaEventCreateWithFlags(&evJoin, cudaEventDisableTiming);
    }
    void* cnt_ptr;  cudaGetSymbolAddress(&cnt_ptr,  g_cnt);
    void* fill_ptr; cudaGetSymbolAddress(&fill_ptr, g_fill);

    // fork: CSR build on s2, GEMM on the main stream
    cudaEventRecord(evFork, 0);
    cudaStreamWaitEvent(s2, evFork, 0);

    gemm_kernel<<<N_NODES / BM, 256>>>(x, W);          // main stream, 625 CTAs

    cudaMemsetAsync(cnt_ptr,  0, N_NODES * sizeof(int), s2);
    cudaMemsetAsync(fill_ptr, 0, N_NODES * sizeof(int), s2);
    hist_kernel <<<EDGE_BLKS, 256, 0, s2>>>(ei);
    scan1_kernel<<<NODE_BLKS, 256, 0, s2>>>();
    scan2_kernel<<<1,         256, 0, s2>>>(NODE_BLKS);
    fill_kernel <<<EDGE_BLKS, 256, 0, s2>>>(ei, ew);

    // join: aggregate needs support (main) + CSR (s2)
    cudaEventRecord(evJoin, s2);
    cudaStreamWaitEvent(0, evJoin, 0);

    aggregate_kernel<<<(N_NODES * 32 + 255) / 256, 256>>>(b, out);
}